// round 14
// baseline (speedup 1.0000x reference)
#include <cuda_runtime.h>

// Aggregation: out[n, g*32+wc, h, w] =
//   sum_{kh,kw} x_reflect[n, g*32+wc, h+kh-1, w+kw-1] * weight[n, wc, kh*3+kw, h, w]
//
// x (8,256,128,128) f32, weight (8,32,9,128,128) f32, out = x shape.
//
// R14 = R4's exact per-warp code with half-size CTAs (128 thr, 6 CTAs/SM,
// grid 8192). Warps/SM (24), regs (80), and the inner instruction stream are
// unchanged; only scheduling granularity changes: finer wave-tail backfill
// and 6 independent tiles' load/drain phases interleaved per SM instead of 3.
// R4 core (best, reproduced twice at 66.0us / DRAM 78%):
// - weights register-resident across all 8 channel groups
// - halo columns via warp shuffle (warp spans a full W=128 row)
// - kh-phase batches of 3 wt + 8 x float4 loads, 32 acc regs,
//   deferred 8-store streaming burst.

namespace {
constexpr int N  = 8;
constexpr int C  = 256;
constexpr int H  = 128;
constexpr int W  = 128;
constexpr int WC = 32;
constexpr int G  = C / WC;   // 8
constexpr int HW = H * W;
constexpr int CS = WC * HW;  // channel-group stride (elements)
constexpr int THREADS = 128;
}

__global__ __launch_bounds__(128, 6)
void agg_kernel(const float* __restrict__ x,
                const float* __restrict__ wt,
                float* __restrict__ out)
{
    const int tid = blockIdx.x * THREADS + threadIdx.x;
    // Decode: w4 (32) fastest -> lane id == w4; then h (128), wc (32), n (8)
    const int w4 = tid & 31;
    const int h  = (tid >> 5) & 127;
    const int wc = (tid >> 12) & 31;
    const int n  = tid >> 17;
    const int w  = w4 << 2;

    // Reflect rows (PAD=1: only -1 and 128 occur)
    const int hr0 = (h == 0)     ? 1     : h - 1;
    const int hr2 = (h == H - 1) ? H - 2 : h + 1;
    const int rows[3] = { hr0, h, hr2 };

    const bool lane_lo = (w4 == 0);
    const bool lane_hi = (w4 == 31);

    const size_t x_n_base = (size_t)n * C * HW;
    const float* xbase = x + x_n_base + (size_t)wc * HW + w;

    const float4* wp = reinterpret_cast<const float4*>(
        wt + ((size_t)(n * WC + wc) * 9) * HW + (size_t)h * W + w);

    float4 acc[G];
    #pragma unroll
    for (int g = 0; g < G; g++)
        acc[g] = make_float4(0.f, 0.f, 0.f, 0.f);

    #pragma unroll
    for (int kh = 0; kh < 3; kh++) {
        // 3 weight float4s for this kh (read-once: evict-first)
        const float4 wA = __ldcs(wp + (kh * 3 + 0) * (HW / 4));
        const float4 wB = __ldcs(wp + (kh * 3 + 1) * (HW / 4));
        const float4 wD = __ldcs(wp + (kh * 3 + 2) * (HW / 4));

        // 8 independent x-row loads, batched back-to-back
        const float* xr = xbase + rows[kh] * W;
        float4 xm[G];
        #pragma unroll
        for (int g = 0; g < G; g++)
            xm[g] = *reinterpret_cast<const float4*>(xr + g * CS);

        #pragma unroll
        for (int g = 0; g < G; g++) {
            const float v1 = xm[g].x, v2 = xm[g].y,
                        v3 = xm[g].z, v4 = xm[g].w;
            // halo via warp shuffle; reflect at row ends is intra-lane
            float v0 = __shfl_up_sync(0xffffffffu, v4, 1);
            float v5 = __shfl_down_sync(0xffffffffu, v1, 1);
            if (lane_lo) v0 = v2;   // col -1  -> col 1
            if (lane_hi) v5 = v3;   // col 128 -> col 126

            acc[g].x = fmaf(v0, wA.x, fmaf(v1, wB.x, fmaf(v2, wD.x, acc[g].x)));
            acc[g].y = fmaf(v1, wA.y, fmaf(v2, wB.y, fmaf(v3, wD.y, acc[g].y)));
            acc[g].z = fmaf(v2, wA.z, fmaf(v3, wB.z, fmaf(v4, wD.z, acc[g].z)));
            acc[g].w = fmaf(v3, wA.w, fmaf(v4, wB.w, fmaf(v5, wD.w, acc[g].w)));
        }
    }

    // One contiguous write burst: 8 streaming float4 stores
    float* ob = out + x_n_base + (size_t)wc * HW + (size_t)h * W + w;
    #pragma unroll
    for (int g = 0; g < G; g++)
        __stcs(reinterpret_cast<float4*>(ob + g * CS), acc[g]);
}

extern "C" void kernel_launch(void* const* d_in, const int* in_sizes, int n_in,
                              void* d_out, int out_size)
{
    const float* x  = (const float*)d_in[0];
    const float* wt = (const float*)d_in[1];
    float* out      = (float*)d_out;

    const int total  = N * WC * H * (W / 4);   // 1,048,576 threads
    const int blocks = total / THREADS;        // 8192
    agg_kernel<<<blocks, THREADS>>>(x, wt, out);
}

// round 15
// speedup vs baseline: 1.0098x; 1.0098x over previous
#include <cuda_runtime.h>

// Aggregation: out[n, g*32+wc, h, w] =
//   sum_{kh,kw} x_reflect[n, g*32+wc, h+kh-1, w+kw-1] * weight[n, wc, kh*3+kw, h, w]
//
// x (8,256,128,128) f32, weight (8,32,9,128,128) f32, out = x shape.
//
// FINAL (best of 14 rounds: 66.0us, DRAM 78%, 6.2 TB/s, rel_err 7.7e-8):
// - DRAM traffic below the naive floor (~372MB measured vs 419MB):
//   * weights register-resident across all 8 channel groups (read once)
//   * halo columns via warp shuffle (a warp spans one full W=128 row);
//     reflect edges are intra-lane swaps
//   * x vertical halos hit in L2 across CTAs
// - kh-outer phases: 3 weight + 8 independent x float4 loads batched
//   back-to-back (11-deep MLP), 32 persistent accumulator registers, all 8
//   output stores as one contiguous streaming burst at the end.
// - 3 CTAs/SM (80 regs, 24 warps/SM), one-shot 4096x256 grid.
// Falsified alternatives (all measured worse or neutral): more warps/less MLP
// (R5), register double-buffering (R6), persistent grid (R7), weight prefetch
// (R8), per-thread cp.async staging (R9), store interleave (R10), cp.async.bulk
// 5KB-burst staging (R12), 128-thread CTAs (R14). DRAM busy pins at 77-79%
// for every load mechanism: interleaved read/write stream ceiling.

namespace {
constexpr int N  = 8;
constexpr int C  = 256;
constexpr int H  = 128;
constexpr int W  = 128;
constexpr int WC = 32;
constexpr int G  = C / WC;   // 8
constexpr int HW = H * W;
constexpr int CS = WC * HW;  // channel-group stride (elements)
}

__global__ __launch_bounds__(256, 3)
void agg_kernel(const float* __restrict__ x,
                const float* __restrict__ wt,
                float* __restrict__ out)
{
    const int tid = blockIdx.x * 256 + threadIdx.x;
    // Decode: w4 (32) fastest -> lane id == w4; then h (128), wc (32), n (8)
    const int w4 = tid & 31;
    const int h  = (tid >> 5) & 127;
    const int wc = (tid >> 12) & 31;
    const int n  = tid >> 17;
    const int w  = w4 << 2;

    // Reflect rows (PAD=1: only -1 and 128 occur)
    const int hr0 = (h == 0)     ? 1     : h - 1;
    const int hr2 = (h == H - 1) ? H - 2 : h + 1;
    const int rows[3] = { hr0, h, hr2 };

    const bool lane_lo = (w4 == 0);
    const bool lane_hi = (w4 == 31);

    const size_t x_n_base = (size_t)n * C * HW;
    const float* xbase = x + x_n_base + (size_t)wc * HW + w;

    const float4* wp = reinterpret_cast<const float4*>(
        wt + ((size_t)(n * WC + wc) * 9) * HW + (size_t)h * W + w);

    float4 acc[G];
    #pragma unroll
    for (int g = 0; g < G; g++)
        acc[g] = make_float4(0.f, 0.f, 0.f, 0.f);

    #pragma unroll
    for (int kh = 0; kh < 3; kh++) {
        // 3 weight float4s for this kh (read-once: evict-first)
        const float4 wA = __ldcs(wp + (kh * 3 + 0) * (HW / 4));
        const float4 wB = __ldcs(wp + (kh * 3 + 1) * (HW / 4));
        const float4 wD = __ldcs(wp + (kh * 3 + 2) * (HW / 4));

        // 8 independent x-row loads, batched back-to-back
        const float* xr = xbase + rows[kh] * W;
        float4 xm[G];
        #pragma unroll
        for (int g = 0; g < G; g++)
            xm[g] = *reinterpret_cast<const float4*>(xr + g * CS);

        #pragma unroll
        for (int g = 0; g < G; g++) {
            const float v1 = xm[g].x, v2 = xm[g].y,
                        v3 = xm[g].z, v4 = xm[g].w;
            // halo via warp shuffle; reflect at row ends is intra-lane
            float v0 = __shfl_up_sync(0xffffffffu, v4, 1);
            float v5 = __shfl_down_sync(0xffffffffu, v1, 1);
            if (lane_lo) v0 = v2;   // col -1  -> col 1
            if (lane_hi) v5 = v3;   // col 128 -> col 126

            acc[g].x = fmaf(v0, wA.x, fmaf(v1, wB.x, fmaf(v2, wD.x, acc[g].x)));
            acc[g].y = fmaf(v1, wA.y, fmaf(v2, wB.y, fmaf(v3, wD.y, acc[g].y)));
            acc[g].z = fmaf(v2, wA.z, fmaf(v3, wB.z, fmaf(v4, wD.z, acc[g].z)));
            acc[g].w = fmaf(v3, wA.w, fmaf(v4, wB.w, fmaf(v5, wD.w, acc[g].w)));
        }
    }

    // One contiguous write burst: 8 streaming float4 stores
    float* ob = out + x_n_base + (size_t)wc * HW + (size_t)h * W + w;
    #pragma unroll
    for (int g = 0; g < G; g++)
        __stcs(reinterpret_cast<float4*>(ob + g * CS), acc[g]);
}

extern "C" void kernel_launch(void* const* d_in, const int* in_sizes, int n_in,
                              void* d_out, int out_size)
{
    const float* x  = (const float*)d_in[0];
    const float* wt = (const float*)d_in[1];
    float* out      = (float*)d_out;

    const int total   = N * WC * H * (W / 4);  // 1,048,576 threads
    const int threads = 256;
    const int blocks  = total / threads;       // 4096
    agg_kernel<<<blocks, threads>>>(x, wt, out);
}